// round 1
// baseline (speedup 1.0000x reference)
#include <cuda_runtime.h>
#include <math.h>

#define BB 64
#define TT 128
#define DD 256
#define HH 1024
#define G3 3072   // useful gate rows: i, g, o (f gate is dead)

// ------------------------- scratch (device globals) -------------------------
__device__ float g_W1[G3 * HH];        // Wih1+Whh1, compacted to i/g/o rows
__device__ float g_part[2 * BB * G3];  // k-split partial gate sums
__device__ float g_h[BB * HH];         // recurrent hidden state
__device__ float g_h0[BB * HH];        // layer-0 output
__device__ float g_imp[BB * DD];       // imputed input

// ------------------------------- init kernels -------------------------------
__global__ void zero_h_kernel() {
    int i = blockIdx.x * blockDim.x + threadIdx.x;
    if (i < BB * HH) g_h[i] = 0.0f;
}

// W1[jj][k] = Wih1[phys][k] + Whh1[phys][k], jj in [0,3072): i/g/o rows only
__global__ void w1_prep_kernel(const float* __restrict__ Wih1,
                               const float* __restrict__ Whh1) {
    int i = blockIdx.x * blockDim.x + threadIdx.x;   // over G3*HH
    int jj = i >> 10;            // /HH
    int k  = i & (HH - 1);
    int phys = jj + (jj >= HH ? HH : 0);             // i:[0,1024) g:+2048 o:+3072
    g_W1[i] = Wih1[phys * HH + k] + Whh1[phys * HH + k];
}

// -------------------------- est + imputation kernel -------------------------
// est[b,d] = h @ Wout^T + bout ; writes out[t-1] for t>=1 ; imputed for t<T.
// grid: 64 CTAs (d-tiles of 4), 256 threads: thread = (b = tid&63, dq = tid>>6)
__global__ __launch_bounds__(256) void est_kernel(
        const float* __restrict__ Wout, const float* __restrict__ bout,
        const float* __restrict__ X, const float* __restrict__ Mm,
        float* __restrict__ out, int t) {
    __shared__ float Hs[64][33];
    int tid = threadIdx.x;
    int b  = tid & 63;
    int dq = tid >> 6;
    int d  = blockIdx.x * 4 + dq;
    const float* wrow = Wout + d * HH;
    float acc = 0.0f;
    for (int kc = 0; kc < HH; kc += 32) {
        #pragma unroll
        for (int i = 0; i < 8; i++) {
            int idx = tid + i * 256;
            int bb = idx >> 5, kk = idx & 31;
            Hs[bb][kk] = g_h[bb * HH + kc + kk];
        }
        __syncthreads();
        #pragma unroll
        for (int kk = 0; kk < 32; kk++)
            acc += Hs[b][kk] * wrow[kc + kk];
        __syncthreads();
    }
    float est = acc + bout[d];
    if (t > 0) out[(b * TT + (t - 1)) * DD + d] = est;
    if (t < TT) {
        int xi = (b * TT + t) * DD + d;
        float m = Mm[xi];
        g_imp[b * DD + d] = m * X[xi] + (1.0f - m) * est;
    }
}

// ------------------------------ gates GEMM ----------------------------------
// Computes part[y][b][jj] = sum over this CTA's k-range of A@W^T for the
// 3072 useful gate rows. mode 0: layer0 (imputed@Wih0 + h@Whh0, remapped rows)
// mode 1: layer1 (h0 @ g_W1, rows already compacted).
// grid: (96 j-tiles of 32, 2 k-splits), 256 threads, micro-tile 4b x 2j.
__global__ __launch_bounds__(256) void gates_gemm(
        int mode, const float* __restrict__ Wa, const float* __restrict__ Wb) {
    const int jt = blockIdx.x * 32;
    const int y  = blockIdx.y;

    const float *A0, *A1, *W0, *W1p;
    int K0, K1, remap;
    if (mode == 0) {
        A0 = g_imp; W0 = Wa; K0 = DD;
        A1 = g_h;   W1p = Wb; K1 = HH;
        remap = 1;
    } else {
        A0 = g_h0;  W0 = g_W1; K0 = HH;
        A1 = nullptr; W1p = nullptr; K1 = 0;
        remap = 0;
    }
    const int Ktot  = K0 + K1;
    const int khalf = Ktot >> 1;               // 640 or 512, both %16==0
    const int kbeg  = y * khalf;
    const int kend  = kbeg + khalf;

    __shared__ __align__(16) float As[16][72];  // [k][b], padded
    __shared__ __align__(16) float Ws[16][36];  // [k][j], padded

    const int tid = threadIdx.x;
    const int tx  = tid & 15;    // j pair
    const int ty  = tid >> 4;    // b quad
    float acc[4][2] = {};

    // staging indices (constant per thread)
    const int sa_k  = tid & 15;
    const int sa_b4 = (tid >> 4) << 2;
    const int sw_j  = tid >> 3;
    const int sw_k  = (tid & 7) << 1;

    for (int kc = kbeg; kc < kend; kc += 16) {
        const float* A; const float* W; int kl, ld;
        if (kc < K0) { A = A0; W = W0;  kl = kc;      ld = K0; }
        else         { A = A1; W = W1p; kl = kc - K0; ld = K1; }

        // stage A tile [64 b x 16 k] -> As[k][b]
        #pragma unroll
        for (int i = 0; i < 4; i++)
            As[sa_k][sa_b4 + i] = A[(sa_b4 + i) * ld + kl + sa_k];

        // stage W tile [32 j x 16 k] -> Ws[k][j]
        {
            int jj = jt + sw_j;
            int phys = jj + ((remap && jj >= HH) ? HH : 0);
            float2 wv = *(const float2*)(W + phys * ld + kl + sw_k);
            Ws[sw_k][sw_j]     = wv.x;
            Ws[sw_k + 1][sw_j] = wv.y;
        }
        __syncthreads();

        #pragma unroll
        for (int kk = 0; kk < 16; kk++) {
            float4 a = *(const float4*)&As[kk][ty << 2];
            float2 w = *(const float2*)&Ws[kk][tx << 1];
            acc[0][0] += a.x * w.x;  acc[0][1] += a.x * w.y;
            acc[1][0] += a.y * w.x;  acc[1][1] += a.y * w.y;
            acc[2][0] += a.z * w.x;  acc[2][1] += a.z * w.y;
            acc[3][0] += a.w * w.x;  acc[3][1] += a.w * w.y;
        }
        __syncthreads();
    }

    float* outp = g_part + y * (BB * G3);
    const int b0 = ty << 2;
    const int j0 = jt + (tx << 1);
    #pragma unroll
    for (int i = 0; i < 4; i++) {
        float2 v = make_float2(acc[i][0], acc[i][1]);
        *(float2*)&outp[(b0 + i) * G3 + j0] = v;
    }
}

// ------------------------------- activation ---------------------------------
// h_out[b,u] = sigmoid(o) * tanh( sigmoid(i) * tanh(g) )
__global__ __launch_bounds__(256) void act_kernel(
        int mode, const float* __restrict__ bih, const float* __restrict__ bhh) {
    int idx = blockIdx.x * blockDim.x + threadIdx.x;  // over BB*HH
    int b = idx >> 10;
    int u = idx & (HH - 1);
    const float* p0 = g_part;
    const float* p1 = g_part + BB * G3;
    int base = b * G3;
    float gi = p0[base + u]        + p1[base + u]        + bih[u]        + bhh[u];
    float gg = p0[base + 1024 + u] + p1[base + 1024 + u] + bih[2048 + u] + bhh[2048 + u];
    float go = p0[base + 2048 + u] + p1[base + 2048 + u] + bih[3072 + u] + bhh[3072 + u];
    float si = 1.0f / (1.0f + expf(-gi));
    float so = 1.0f / (1.0f + expf(-go));
    float h  = so * tanhf(si * tanhf(gg));
    if (mode == 0) g_h0[idx] = h;
    else           g_h[idx]  = h;
}

// ------------------------------ h_final copy ---------------------------------
__global__ void copy_h_kernel(float* __restrict__ out) {
    int i = blockIdx.x * blockDim.x + threadIdx.x;
    if (i < BB * HH) out[BB * TT * DD + i] = g_h[i];
}

// --------------------------------- launch ------------------------------------
extern "C" void kernel_launch(void* const* d_in, const int* in_sizes, int n_in,
                              void* d_out, int out_size) {
    const float* X    = (const float*)d_in[0];
    const float* Mm   = (const float*)d_in[1];
    const float* Wih0 = (const float*)d_in[2];
    const float* Whh0 = (const float*)d_in[3];
    const float* bih0 = (const float*)d_in[4];
    const float* bhh0 = (const float*)d_in[5];
    const float* Wih1 = (const float*)d_in[6];
    const float* Whh1 = (const float*)d_in[7];
    const float* bih1 = (const float*)d_in[8];
    const float* bhh1 = (const float*)d_in[9];
    const float* Wout = (const float*)d_in[10];
    const float* bout = (const float*)d_in[11];
    float* out = (float*)d_out;

    zero_h_kernel<<<(BB * HH + 255) / 256, 256>>>();
    w1_prep_kernel<<<(G3 * HH) / 256, 256>>>(Wih1, Whh1);

    dim3 gg(G3 / 32, 2);
    for (int t = 0; t < TT; t++) {
        est_kernel<<<DD / 4, 256>>>(Wout, bout, X, Mm, out, t);
        gates_gemm<<<gg, 256>>>(0, Wih0, Whh0);
        act_kernel<<<(BB * HH) / 256, 256>>>(0, bih0, bhh0);
        gates_gemm<<<gg, 256>>>(1, nullptr, nullptr);
        act_kernel<<<(BB * HH) / 256, 256>>>(1, bih1, bhh1);
    }
    // final est from h_final -> out[:, T-1, :]
    est_kernel<<<DD / 4, 256>>>(Wout, bout, X, Mm, out, TT);

    if (out_size >= BB * TT * DD + BB * HH)
        copy_h_kernel<<<(BB * HH + 255) / 256, 256>>>(out);
}

// round 2
// speedup vs baseline: 1.6711x; 1.6711x over previous
#include <cuda_runtime.h>
#include <math.h>

#define BB 64
#define TT 128
#define DD 256
#define HH 1024
#define G3 3072   // useful gate rows: i, g, o (f gate is dead)
#define SPLIT 4

// ------------------------- scratch (device globals) -------------------------
__device__ float g_W1[G3 * HH];            // Wih1+Whh1, compacted to i/g/o rows
__device__ float g_part[SPLIT * BB * G3];  // k-split partial gate sums
__device__ float g_h[BB * HH];             // recurrent hidden state
__device__ float g_h0[BB * HH];            // layer-0 output
__device__ float g_imp[BB * DD];           // imputed input

// ------------------------------- helpers ------------------------------------
__device__ __forceinline__ float to_tf32(float x) {
    float y;
    asm("cvt.rna.tf32.f32 %0, %1;" : "=f"(y) : "f"(x));
    return y;
}

__device__ __forceinline__ void mma_tf32(float* d, const unsigned* a, const unsigned* b) {
    asm volatile(
        "mma.sync.aligned.m16n8k8.row.col.f32.tf32.tf32.f32 "
        "{%0,%1,%2,%3},{%4,%5,%6,%7},{%8,%9},{%0,%1,%2,%3};"
        : "+f"(d[0]), "+f"(d[1]), "+f"(d[2]), "+f"(d[3])
        : "r"(a[0]), "r"(a[1]), "r"(a[2]), "r"(a[3]),
          "r"(b[0]), "r"(b[1]));
}

// ------------------------------- init kernels -------------------------------
__global__ void zero_h_kernel() {
    int i = blockIdx.x * blockDim.x + threadIdx.x;
    if (i < BB * HH) g_h[i] = 0.0f;
}

// W1[jj][k] = Wih1[phys][k] + Whh1[phys][k], jj in [0,3072): i/g/o rows only
__global__ void w1_prep_kernel(const float* __restrict__ Wih1,
                               const float* __restrict__ Whh1) {
    int i = blockIdx.x * blockDim.x + threadIdx.x;   // over G3*HH
    int jj = i >> 10;            // /HH
    int k  = i & (HH - 1);
    int phys = jj + (jj >= HH ? HH : 0);             // i:[0,1024) g:+2048 o:+3072
    g_W1[i] = Wih1[phys * HH + k] + Whh1[phys * HH + k];
}

// -------------------------- est + imputation kernel -------------------------
__global__ __launch_bounds__(256) void est_kernel(
        const float* __restrict__ Wout, const float* __restrict__ bout,
        const float* __restrict__ X, const float* __restrict__ Mm,
        float* __restrict__ out, int t) {
    __shared__ float Hs[64][33];
    int tid = threadIdx.x;
    int b  = tid & 63;
    int dq = tid >> 6;
    int d  = blockIdx.x * 4 + dq;
    const float* wrow = Wout + d * HH;
    float acc = 0.0f;
    for (int kc = 0; kc < HH; kc += 32) {
        #pragma unroll
        for (int i = 0; i < 8; i++) {
            int idx = tid + i * 256;
            int bb = idx >> 5, kk = idx & 31;
            Hs[bb][kk] = g_h[bb * HH + kc + kk];
        }
        __syncthreads();
        #pragma unroll
        for (int kk = 0; kk < 32; kk++)
            acc += Hs[b][kk] * wrow[kc + kk];
        __syncthreads();
    }
    float est = acc + bout[d];
    if (t > 0) out[(b * TT + (t - 1)) * DD + d] = est;
    if (t < TT) {
        int xi = (b * TT + t) * DD + d;
        float m = Mm[xi];
        g_imp[b * DD + d] = m * X[xi] + (1.0f - m) * est;
    }
}

// --------------------------- gates GEMM (tensor core) ------------------------
// C[64 b x 3072 j] partial sums over this CTA's k-range, tf32 mma.
// CTA: 256 thr (8 warps: 4 M-warps x 2 N-warps), tile M=64, N=64, k-chunk 32.
// grid: (48 j-tiles, SPLIT k-splits)
// mode 0: layer0  A = [imp(256) | h(1024)], W = [Wih0 | Whh0] (rows remapped)
// mode 1: layer1  A = h0(1024), W = g_W1 (rows compacted already)
#define SSTR 40   // smem row stride (floats): conflict-free frag reads

__global__ __launch_bounds__(256) void gates_mma(
        int mode, const float* __restrict__ Wa, const float* __restrict__ Wb) {
    __shared__ __align__(16) float As[64][SSTR];   // [b][k]
    __shared__ __align__(16) float Bs[64][SSTR];   // [j][k]

    const int jt = blockIdx.x * 64;
    const int y  = blockIdx.y;

    const int Ktot = (mode == 0) ? (DD + HH) : HH;   // 1280 / 1024
    const int kper = Ktot / SPLIT;                   // 320 / 256
    const int kbeg = y * kper;
    const int nch  = kper >> 5;                      // 10 / 8

    const int tid  = threadIdx.x;
    const int warp = tid >> 5, lane = tid & 31;
    const int mw = warp & 3, nw = warp >> 2;
    const int m0 = mw << 4;          // 0,16,32,48
    const int nb = nw << 5;          // 0,32
    const int r  = lane >> 2, c = lane & 3;

    float acc[4][4] = {};            // [n-tile][c-regs]
    float4 areg[2], breg[2];

    // staging map: idx = tid + 256*i ; row = idx>>3 (0..63), k4 = (idx&7)*4
    const int s_row = tid >> 3;
    const int s_k4  = (tid & 7) << 2;

    // ---- load chunk `ch` into registers ----
    auto loadchunk = [&](int ch) {
        const int kc = kbeg + (ch << 5);
        const float* A; const float* W; int ld, kl;
        if (mode == 0) {
            if (kc < DD) { A = g_imp; W = Wa; ld = DD; kl = kc; }
            else         { A = g_h;   W = Wb; ld = HH; kl = kc - DD; }
        } else           { A = g_h0;  W = g_W1; ld = HH; kl = kc; }
        #pragma unroll
        for (int i = 0; i < 2; i++) {
            int row = s_row + (i << 5);
            areg[i] = *(const float4*)(A + row * ld + kl + s_k4);
            int jj = jt + row;
            int phys = (mode == 0 && jj >= HH) ? jj + HH : jj;
            breg[i] = *(const float4*)(W + phys * ld + kl + s_k4);
        }
    };

    // ---- store registers to smem (with tf32 rounding) ----
    auto storechunk = [&]() {
        #pragma unroll
        for (int i = 0; i < 2; i++) {
            int row = s_row + (i << 5);
            float4 a = areg[i], b = breg[i];
            a.x = to_tf32(a.x); a.y = to_tf32(a.y); a.z = to_tf32(a.z); a.w = to_tf32(a.w);
            b.x = to_tf32(b.x); b.y = to_tf32(b.y); b.z = to_tf32(b.z); b.w = to_tf32(b.w);
            *(float4*)&As[row][s_k4] = a;
            *(float4*)&Bs[row][s_k4] = b;
        }
    };

    loadchunk(0);
    for (int ch = 0; ch < nch; ch++) {
        __syncthreads();
        storechunk();
        __syncthreads();
        if (ch + 1 < nch) loadchunk(ch + 1);

        #pragma unroll
        for (int s = 0; s < 4; s++) {
            const int kb = s << 3;
            unsigned a[4];
            a[0] = __float_as_uint(As[m0 + r    ][kb + c    ]);
            a[1] = __float_as_uint(As[m0 + r + 8][kb + c    ]);
            a[2] = __float_as_uint(As[m0 + r    ][kb + c + 4]);
            a[3] = __float_as_uint(As[m0 + r + 8][kb + c + 4]);
            #pragma unroll
            for (int t = 0; t < 4; t++) {
                const int n0 = nb + (t << 3);
                unsigned b[2];
                b[0] = __float_as_uint(Bs[n0 + r][kb + c    ]);
                b[1] = __float_as_uint(Bs[n0 + r][kb + c + 4]);
                mma_tf32(acc[t], a, b);
            }
        }
    }

    float* outp = g_part + y * (BB * G3);
    #pragma unroll
    for (int t = 0; t < 4; t++) {
        const int j0 = jt + nb + (t << 3) + (c << 1);
        *(float2*)&outp[(m0 + r    ) * G3 + j0] = make_float2(acc[t][0], acc[t][1]);
        *(float2*)&outp[(m0 + r + 8) * G3 + j0] = make_float2(acc[t][2], acc[t][3]);
    }
}

// ------------------------------- activation ---------------------------------
// h_out[b,u] = sigmoid(o) * tanh( sigmoid(i) * tanh(g) )
__global__ __launch_bounds__(256) void act_kernel(
        int mode, const float* __restrict__ bih, const float* __restrict__ bhh) {
    int idx = blockIdx.x * blockDim.x + threadIdx.x;  // over BB*HH
    int b = idx >> 10;
    int u = idx & (HH - 1);
    int base = b * G3;
    float gi = bih[u]        + bhh[u];
    float gg = bih[2048 + u] + bhh[2048 + u];
    float go = bih[3072 + u] + bhh[3072 + u];
    #pragma unroll
    for (int y = 0; y < SPLIT; y++) {
        const float* p = g_part + y * (BB * G3);
        gi += p[base + u];
        gg += p[base + 1024 + u];
        go += p[base + 2048 + u];
    }
    float si = 1.0f / (1.0f + expf(-gi));
    float so = 1.0f / (1.0f + expf(-go));
    float h  = so * tanhf(si * tanhf(gg));
    if (mode == 0) g_h0[idx] = h;
    else           g_h[idx]  = h;
}

// ------------------------------ h_final copy ---------------------------------
__global__ void copy_h_kernel(float* __restrict__ out) {
    int i = blockIdx.x * blockDim.x + threadIdx.x;
    if (i < BB * HH) out[BB * TT * DD + i] = g_h[i];
}

// --------------------------------- launch ------------------------------------
extern "C" void kernel_launch(void* const* d_in, const int* in_sizes, int n_in,
                              void* d_out, int out_size) {
    const float* X    = (const float*)d_in[0];
    const float* Mm   = (const float*)d_in[1];
    const float* Wih0 = (const float*)d_in[2];
    const float* Whh0 = (const float*)d_in[3];
    const float* bih0 = (const float*)d_in[4];
    const float* bhh0 = (const float*)d_in[5];
    const float* Wih1 = (const float*)d_in[6];
    const float* Whh1 = (const float*)d_in[7];
    const float* bih1 = (const float*)d_in[8];
    const float* bhh1 = (const float*)d_in[9];
    const float* Wout = (const float*)d_in[10];
    const float* bout = (const float*)d_in[11];
    float* out = (float*)d_out;

    zero_h_kernel<<<(BB * HH + 255) / 256, 256>>>();
    w1_prep_kernel<<<(G3 * HH) / 256, 256>>>(Wih1, Whh1);

    dim3 gg(G3 / 64, SPLIT);
    for (int t = 0; t < TT; t++) {
        est_kernel<<<DD / 4, 256>>>(Wout, bout, X, Mm, out, t);
        gates_mma<<<gg, 256>>>(0, Wih0, Whh0);
        act_kernel<<<(BB * HH) / 256, 256>>>(0, bih0, bhh0);
        gates_mma<<<gg, 256>>>(1, nullptr, nullptr);
        act_kernel<<<(BB * HH) / 256, 256>>>(1, bih1, bhh1);
    }
    // final est from h_final -> out[:, T-1, :]
    est_kernel<<<DD / 4, 256>>>(Wout, bout, X, Mm, out, TT);

    if (out_size >= BB * TT * DD + BB * HH)
        copy_h_kernel<<<(BB * HH + 255) / 256, 256>>>(out);
}

// round 3
// speedup vs baseline: 3.9628x; 2.3714x over previous
#include <cuda_runtime.h>
#include <math.h>

#define BB 64
#define TT 128
#define DD 256
#define HH 1024
#define NCTA 128
#define NTHR 256
#define CH 64          // k-chunk per pipeline stage
#define A_ST 68        // smem row stride (floats)

// ------------------------- device globals -------------------------
__device__ float g_WP1[NCTA * 32 * HH];   // per-CTA P1 slab: 24 gate rows (Whh0 i/g/o) + 8 Wout rows (cta<32)
__device__ float g_WP2[NCTA * 24 * DD];   // per-CTA Wih0 i/g/o rows
__device__ float g_WP3[NCTA * 24 * HH];   // per-CTA (Wih1+Whh1) i/g/o rows
__device__ float g_B0[NCTA * 24];         // bih0+bhh0 (i/g/o)
__device__ float g_B1[NCTA * 24];         // bih1+bhh1 (i/g/o)
__device__ float g_h[BB * HH];
__device__ float g_h0[BB * HH];
__device__ float g_imp[BB * DD];
__device__ unsigned g_barcnt;

// ------------------------- helpers -------------------------
__device__ __forceinline__ float to_tf32(float x) {
    float y;
    asm("cvt.rna.tf32.f32 %0, %1;" : "=f"(y) : "f"(x));
    return y;
}
__device__ __forceinline__ void mma_tf32(float* d, const unsigned* a, const unsigned* b) {
    asm volatile(
        "mma.sync.aligned.m16n8k8.row.col.f32.tf32.tf32.f32 "
        "{%0,%1,%2,%3},{%4,%5,%6,%7},{%8,%9},{%0,%1,%2,%3};"
        : "+f"(d[0]), "+f"(d[1]), "+f"(d[2]), "+f"(d[3])
        : "r"(a[0]), "r"(a[1]), "r"(a[2]), "r"(a[3]), "r"(b[0]), "r"(b[1]));
}
__device__ __forceinline__ void cpa16(unsigned s, const float* g) {
    asm volatile("cp.async.cg.shared.global [%0], [%1], 16;" :: "r"(s), "l"(g));
}
__device__ __forceinline__ void cpcommit() { asm volatile("cp.async.commit_group;"); }
__device__ __forceinline__ void cpwait0()  { asm volatile("cp.async.wait_group 0;"); }
__device__ __forceinline__ void cpwait1()  { asm volatile("cp.async.wait_group 1;"); }

// smem float-index layout
__device__ __forceinline__ int As_off(int st, int kw, int row, int k) {
    return (((st * 2 + kw) * 64) + row) * A_ST + k;
}
__device__ __forceinline__ int Ws_off(int st, int kw, int row, int k) {
    return 17408 + (((st * 2 + kw) * 32) + row) * A_ST + k;
}
#define RED_OFF 26112
#define SMEM_FLOATS 28160

// ------------------------- init / pack kernels -------------------------
__global__ void zero_kernel() {
    int i = blockIdx.x * blockDim.x + threadIdx.x;
    if (i == 0) g_barcnt = 0;
    if (i < BB * HH) g_h[i] = 0.0f;
}
__device__ __forceinline__ int phys_row(int cta, int r) {  // r in [0,24)
    int u = cta * 8 + (r & 7);
    int g = r >> 3;                       // 0=i,1=g,2=o
    return u + (g == 0 ? 0 : (g == 1 ? 2048 : 3072));
}
__global__ void pack1(const float* __restrict__ Whh0, const float* __restrict__ Wout) {
    int idx = blockIdx.x * blockDim.x + threadIdx.x;          // < 128*32*1024
    int cta = idx >> 15, r = (idx >> 10) & 31, k = idx & 1023;
    float v = 0.0f;
    if (r < 24)            v = Whh0[phys_row(cta, r) * HH + k];
    else if (cta < 32)     v = Wout[(cta * 8 + (r - 24)) * HH + k];
    g_WP1[idx] = to_tf32(v);
}
__global__ void pack2(const float* __restrict__ Wih0) {
    int idx = blockIdx.x * blockDim.x + threadIdx.x;          // < 128*24*256
    int cta = idx / 6144, rem = idx % 6144, r = rem >> 8, k = rem & 255;
    g_WP2[idx] = to_tf32(Wih0[phys_row(cta, r) * DD + k]);
}
__global__ void pack3(const float* __restrict__ Wih1, const float* __restrict__ Whh1) {
    int idx = blockIdx.x * blockDim.x + threadIdx.x;          // < 128*24*1024
    int cta = idx / 24576, r = (idx >> 10) % 24, k = idx & 1023;
    int p = phys_row(cta, r);
    g_WP3[idx] = to_tf32(Wih1[p * HH + k] + Whh1[p * HH + k]);
}
__global__ void packB(const float* __restrict__ bih0, const float* __restrict__ bhh0,
                      const float* __restrict__ bih1, const float* __restrict__ bhh1) {
    int idx = blockIdx.x * blockDim.x + threadIdx.x;          // < 128*24
    if (idx >= NCTA * 24) return;
    int p = phys_row(idx / 24, idx % 24);
    g_B0[idx] = bih0[p] + bhh0[p];
    g_B1[idx] = bih1[p] + bhh1[p];
}

// ------------------------- persistent kernel pieces -------------------------
__device__ __forceinline__ void load_stage(unsigned smb, int st,
        const float* A, int ldA, const float* W, int ldW,
        int khalf, int it, int R, int tid) {
    int kbase = it * CH;
    #pragma unroll
    for (int u = tid; u < 2048; u += NTHR) {                  // A: 2 kw x 64 rows x 16 segs
        int kw = u >> 10, row = (u >> 4) & 63, seg = (u & 15) << 2;
        cpa16(smb + 4u * As_off(st, kw, row, seg), A + row * ldA + kw * khalf + kbase + seg);
    }
    #pragma unroll
    for (int u = tid; u < 1024; u += NTHR) {                  // W: 2 kw x 32 rows x 16 segs
        int kw = u >> 9, row = (u >> 4) & 31, seg = (u & 15) << 2;
        if (row < R)
            cpa16(smb + 4u * Ws_off(st, kw, row, seg), W + row * ldW + kw * khalf + kbase + seg);
    }
    cpcommit();
}

template <int NBLK>
__device__ __forceinline__ void compute_chunk(const float* sm, int st, int kw,
        int m0, int r, int c, float acc[4][4]) {
    #pragma unroll
    for (int s = 0; s < 8; s++) {
        int kb = s * 8;
        unsigned a[4];
        a[0] = __float_as_uint(sm[As_off(st, kw, m0 + r,     kb + c)]);
        a[1] = __float_as_uint(sm[As_off(st, kw, m0 + r + 8, kb + c)]);
        a[2] = __float_as_uint(sm[As_off(st, kw, m0 + r,     kb + c + 4)]);
        a[3] = __float_as_uint(sm[As_off(st, kw, m0 + r + 8, kb + c + 4)]);
        #pragma unroll
        for (int blk = 0; blk < NBLK; blk++) {
            unsigned b[2];
            b[0] = __float_as_uint(sm[Ws_off(st, kw, blk * 8 + r, kb + c)]);
            b[1] = __float_as_uint(sm[Ws_off(st, kw, blk * 8 + r, kb + c + 4)]);
            mma_tf32(acc[blk], a, b);
        }
    }
}

template <int NBLK>
__device__ __forceinline__ void run_phase(unsigned smb, const float* sm,
        const float* A, int ldA, const float* W, int ldW, int khalf, int R,
        float acc[4][4], int tid, int kw, int m0, int r, int c) {
    int nit = khalf / CH;
    load_stage(smb, 0, A, ldA, W, ldW, khalf, 0, R, tid);
    for (int it = 0; it < nit; it++) {
        if (it + 1 < nit) {
            load_stage(smb, (it + 1) & 1, A, ldA, W, ldW, khalf, it + 1, R, tid);
            cpwait1();
        } else {
            cpwait0();
        }
        __syncthreads();
        compute_chunk<NBLK>(sm, it & 1, kw, m0, r, c, acc);
        __syncthreads();
    }
}

__device__ __forceinline__ void reduce_blocks(float* red, float acc[4][4],
        int kw, int mw, int lane, int b0, int b1) {
    __syncthreads();
    if (kw == 1)
        for (int blk = b0; blk <= b1; blk++)
            #pragma unroll
            for (int q = 0; q < 4; q++)
                red[((mw * 4 + blk) * 32 + lane) * 4 + q] = acc[blk][q];
    __syncthreads();
    if (kw == 0)
        for (int blk = b0; blk <= b1; blk++)
            #pragma unroll
            for (int q = 0; q < 4; q++)
                acc[blk][q] += red[((mw * 4 + blk) * 32 + lane) * 4 + q];
    __syncthreads();
}

__device__ __forceinline__ void gridbar(unsigned* barno) {
    __syncthreads();
    (*barno)++;
    if (threadIdx.x == 0) {
        __threadfence();
        atomicAdd(&g_barcnt, 1u);
        unsigned target = (*barno) * NCTA, v;
        do {
            asm volatile("ld.acquire.gpu.global.u32 %0, [%1];" : "=r"(v) : "l"(&g_barcnt));
        } while (v < target);
    }
    __syncthreads();
}

// ------------------------- the persistent kernel -------------------------
__global__ void __launch_bounds__(NTHR, 1) rnn_persist(
        const float* __restrict__ X, const float* __restrict__ Mm,
        const float* __restrict__ bout, float* __restrict__ out) {
    extern __shared__ float sm[];
    unsigned smb = (unsigned)__cvta_generic_to_shared(sm);
    float* red = sm + RED_OFF;
    const int cta = blockIdx.x, tid = threadIdx.x;
    const int warp = tid >> 5, lane = tid & 31;
    const int mw = warp & 3, kw = warp >> 2;
    const int m0 = mw << 4, r = lane >> 2, c = lane & 3;
    const bool has_est = (cta < 32);
    const float* WP1 = g_WP1 + cta * 32 * HH;
    const float* WP2 = g_WP2 + cta * 24 * DD;
    const float* WP3 = g_WP3 + cta * 24 * HH;
    const float* B0p = g_B0 + cta * 24;
    const float* B1p = g_B1 + cta * 24;
    const int u0 = cta * 8;
    unsigned barno = 0;
    float acc[4][4];

    for (int t = 0;; t++) {
        const bool last = (t == TT);
        if (last) {  // h_final -> out tail
            #pragma unroll
            for (int i = tid; i < 512; i += NTHR)
                out[BB * TT * DD + cta * 512 + i] = g_h[cta * 512 + i];
            if (!has_est) break;
        }
        // ---- P1: [gates0 h-part | est] = h @ WP1^T  (k=1024) ----
        #pragma unroll
        for (int blk = 0; blk < 4; blk++)
            #pragma unroll
            for (int q = 0; q < 4; q++) acc[blk][q] = 0.0f;
        if (has_est)
            run_phase<4>(smb, sm, g_h, HH, WP1, HH, 512, 32, acc, tid, kw, m0, r, c);
        else
            run_phase<3>(smb, sm, g_h, HH, WP1, HH, 512, 24, acc, tid, kw, m0, r, c);

        if (has_est) {
            reduce_blocks(red, acc, kw, mw, lane, 3, 3);
            if (kw == 0) {   // est epilogue: write out[t-1], compute imputed
                int d0 = cta * 8;
                #pragma unroll
                for (int half = 0; half < 2; half++) {
                    int b = m0 + r + half * 8;
                    #pragma unroll
                    for (int j = 0; j < 2; j++) {
                        int d = d0 + 2 * c + j;
                        float e = acc[3][half * 2 + j] + bout[d];
                        if (t > 0) out[(b * TT + (t - 1)) * DD + d] = e;
                        if (t < TT) {
                            int xi = (b * TT + t) * DD + d;
                            float m = Mm[xi];
                            g_imp[b * DD + d] = to_tf32(m * X[xi] + (1.0f - m) * e);
                        }
                    }
                }
            }
        }
        if (last) break;
        gridbar(&barno);

        // ---- P2: gates0 += imputed @ WP2^T (k=256), then act0 -> h0 ----
        run_phase<3>(smb, sm, g_imp, DD, WP2, DD, 128, 24, acc, tid, kw, m0, r, c);
        reduce_blocks(red, acc, kw, mw, lane, 0, 2);
        if (kw == 0) {
            #pragma unroll
            for (int half = 0; half < 2; half++) {
                int b = m0 + r + half * 8;
                float2 hv;
                #pragma unroll
                for (int j = 0; j < 2; j++) {
                    int col = 2 * c + j;
                    float gi = acc[0][half * 2 + j] + B0p[col];
                    float gg = acc[1][half * 2 + j] + B0p[8 + col];
                    float go = acc[2][half * 2 + j] + B0p[16 + col];
                    float si = 1.0f / (1.0f + expf(-gi));
                    float so = 1.0f / (1.0f + expf(-go));
                    (&hv.x)[j] = to_tf32(so * tanhf(si * tanhf(gg)));
                }
                *(float2*)&g_h0[b * HH + u0 + 2 * c] = hv;
            }
        }
        gridbar(&barno);

        // ---- P3: gates1 = h0 @ WP3^T (k=1024), act1 -> h ----
        #pragma unroll
        for (int blk = 0; blk < 3; blk++)
            #pragma unroll
            for (int q = 0; q < 4; q++) acc[blk][q] = 0.0f;
        run_phase<3>(smb, sm, g_h0, HH, WP3, HH, 512, 24, acc, tid, kw, m0, r, c);
        reduce_blocks(red, acc, kw, mw, lane, 0, 2);
        if (kw == 0) {
            #pragma unroll
            for (int half = 0; half < 2; half++) {
                int b = m0 + r + half * 8;
                float2 hv;
                #pragma unroll
                for (int j = 0; j < 2; j++) {
                    int col = 2 * c + j;
                    float gi = acc[0][half * 2 + j] + B1p[col];
                    float gg = acc[1][half * 2 + j] + B1p[8 + col];
                    float go = acc[2][half * 2 + j] + B1p[16 + col];
                    float si = 1.0f / (1.0f + expf(-gi));
                    float so = 1.0f / (1.0f + expf(-go));
                    (&hv.x)[j] = to_tf32(so * tanhf(si * tanhf(gg)));
                }
                *(float2*)&g_h[b * HH + u0 + 2 * c] = hv;
            }
        }
        gridbar(&barno);
    }
}

// ------------------------------- launch --------------------------------
extern "C" void kernel_launch(void* const* d_in, const int* in_sizes, int n_in,
                              void* d_out, int out_size) {
    const float* X    = (const float*)d_in[0];
    const float* Mm   = (const float*)d_in[1];
    const float* Wih0 = (const float*)d_in[2];
    const float* Whh0 = (const float*)d_in[3];
    const float* bih0 = (const float*)d_in[4];
    const float* bhh0 = (const float*)d_in[5];
    const float* Wih1 = (const float*)d_in[6];
    const float* Whh1 = (const float*)d_in[7];
    const float* bih1 = (const float*)d_in[8];
    const float* bhh1 = (const float*)d_in[9];
    const float* Wout = (const float*)d_in[10];
    const float* bout = (const float*)d_in[11];
    float* out = (float*)d_out;

    static int smem_set = 0;
    (void)smem_set;
    cudaFuncSetAttribute(rnn_persist, cudaFuncAttributeMaxDynamicSharedMemorySize,
                         SMEM_FLOATS * sizeof(float));

    zero_kernel<<<256, 256>>>();
    pack1<<<(NCTA * 32 * HH) / 256, 256>>>(Whh0, Wout);
    pack2<<<(NCTA * 24 * DD) / 256, 256>>>(Wih0);
    pack3<<<(NCTA * 24 * HH) / 256, 256>>>(Wih1, Whh1);
    packB<<<(NCTA * 24 + 255) / 256, 256>>>(bih0, bhh0, bih1, bhh1);
    rnn_persist<<<NCTA, NTHR, SMEM_FLOATS * sizeof(float)>>>(X, Mm, bout, out);
}